// round 1
// baseline (speedup 1.0000x reference)
#include <cuda_runtime.h>
#include <cuda_bf16.h>
#include <math.h>

#define N1 6001
#define DD 64
#define LL 200
#define BB 32
#define PP (BB*LL)      // 6400
#define QT 32
#define STR 68          // padded smem row stride (floats), keeps float4 alignment, kills bank conflicts
#define MAXNZ 1024

// ---------------- device scratch (no allocations allowed) ----------------
__device__ float g_h[N1*DD];
__device__ float g_wh1[N1];
__device__ float g_wh2[N1];
__device__ float g_hmean[DD];
__device__ float g_gat[PP*DD];
__device__ float g_trans[PP*DD];
__device__ float g_seqs[PP*DD];
__device__ float g_E1[PP*DD];
__device__ float g_E2[PP*DD];
__device__ float g_final[PP*DD];

__device__ __forceinline__ float fast_rcp(float u){
    // u >= 1 always here (u = 1 + positive). Bit-hack + 2 Newton: rel err ~1e-6, no MUFU.
    float y = __int_as_float(0x7EF311C3 - __float_as_int(u));
    y = y * (2.0f - u*y);
    y = y * (2.0f - u*y);
    return y;
}

// ---------------- K1: h_item = emb @ W_item ; wh1/wh2 ----------------
__global__ void k1_hitem(const float* __restrict__ emb, const float* __restrict__ Wi,
                         const float* __restrict__ ai){
    __shared__ float Ws[DD*DD];
    __shared__ float as_[2*DD];
    __shared__ float hrow[4][DD];
    int t = threadIdx.x;
    for (int i=t;i<DD*DD;i+=256) Ws[i]=Wi[i];
    if (t<2*DD) as_[t]=ai[t];
    __syncthreads();
    int r = blockIdx.x*4 + (t>>6);
    int d = t&63;
    float acc=0.f;
    if (r<N1){
        const float* er = emb + r*DD;
        #pragma unroll 16
        for(int k=0;k<DD;k++) acc = fmaf(er[k], Ws[k*DD+d], acc);
        g_h[r*DD+d]=acc;
    }
    hrow[t>>6][d]=acc;
    __syncthreads();
    int w = t>>5, lane=t&31;
    int pl = w>>1, sel=w&1;
    int rr = blockIdx.x*4+pl;
    if (rr<N1){
        float s = hrow[pl][lane]*as_[sel*DD+lane] + hrow[pl][lane+32]*as_[sel*DD+lane+32];
        #pragma unroll
        for(int o=16;o>0;o>>=1) s += __shfl_xor_sync(0xffffffffu,s,o);
        if(lane==0){ if(sel) g_wh2[rr]=s; else g_wh1[rr]=s; }
    }
}

// ---------------- K1b: column mean of h_item (fallback for empty adj rows) ----------------
__global__ void k1b_hmean(){
    int d = blockIdx.x; int t=threadIdx.x;
    float s=0.f;
    for(int r=t;r<N1;r+=256) s += g_h[r*DD+d];
    __shared__ float red[256];
    red[t]=s; __syncthreads();
    for(int o=128;o>0;o>>=1){ if(t<o) red[t]+=red[t+o]; __syncthreads(); }
    if(t==0) g_hmean[d]=red[0]*(1.0f/(float)N1);
}

// ---------------- K2a: sparse GAT row per sequence position ----------------
__global__ void k2a_gat(const float* __restrict__ adj, const int* __restrict__ logs){
    __shared__ int   s_idx[MAXNZ];
    __shared__ float s_val[MAXNZ];
    __shared__ float s_e[MAXNZ];
    __shared__ int wsum[8]; __shared__ int woff[8]; __shared__ int s_n;
    __shared__ float wred[8];
    __shared__ float pg[4][DD], pt[4][DD];
    int t=threadIdx.x, lane=t&31, w=t>>5;
    int p=blockIdx.x;
    int i=logs[p];
    const float* row = adj + (size_t)i*(size_t)N1;
    // pass A: count nonzeros (coalesced)
    int c=0;
    for(int j=t;j<N1;j+=256) c += (row[j]>0.f)?1:0;
    int sc=c;
    #pragma unroll
    for(int o=1;o<32;o<<=1){ int v=__shfl_up_sync(0xffffffffu,sc,o); if(lane>=o) sc+=v; }
    if(lane==31) wsum[w]=sc;
    __syncthreads();
    if(t<8){
        int v=wsum[t]; int iv=v;
        #pragma unroll
        for(int o=1;o<8;o<<=1){ int u=__shfl_up_sync(0x000000ffu,iv,o); if(t>=o) iv+=u; }
        woff[t]=iv-v;
        if(t==7) s_n=iv;
    }
    __syncthreads();
    // pass B: deterministic compaction (L1-hot second pass)
    int off = woff[w] + (sc - c);
    for(int j=t;j<N1;j+=256){
        float a=row[j];
        if(a>0.f){ if(off<MAXNZ){ s_idx[off]=j; s_val[off]=a; } off++; }
    }
    __syncthreads();
    int n = s_n; if(n>MAXNZ) n=MAXNZ;
    float wh1i = g_wh1[i];
    // e = leaky_relu(wh1[i]+wh2[j]); block max
    float m=-1e30f;
    for(int k=t;k<n;k+=256){
        float e = wh1i + g_wh2[s_idx[k]];
        e = (e>0.f)? e : 0.01f*e;
        s_e[k]=e;
        m = fmaxf(m,e);
    }
    #pragma unroll
    for(int o=16;o>0;o>>=1) m=fmaxf(m,__shfl_xor_sync(0xffffffffu,m,o));
    if(lane==0) wred[w]=m;
    __syncthreads();
    float M=wred[0];
    #pragma unroll
    for(int k=1;k<8;k++) M=fmaxf(M,wred[k]);
    __syncthreads();   // all M-reads done before wred reuse
    // weights + denom
    float ds=0.f;
    for(int k=t;k<n;k+=256){
        float wv = __expf(s_e[k]-M);
        s_e[k]=wv; ds+=wv;
    }
    #pragma unroll
    for(int o=16;o>0;o>>=1) ds += __shfl_xor_sync(0xffffffffu,ds,o);
    if(lane==0) wred[w]=ds;
    __syncthreads();
    float den=0.f;
    #pragma unroll
    for(int k=0;k<8;k++) den+=wred[k];
    // weighted accumulation of h_item rows (L2-resident gathers)
    int d=t&63, g4=t>>6;
    float ga=0.f, ta=0.f;
    for(int k=g4;k<n;k+=4){
        float hv = g_h[s_idx[k]*DD+d];
        ga = fmaf(s_e[k],hv,ga);
        ta = fmaf(s_val[k],hv,ta);
    }
    pg[g4][d]=ga; pt[g4][d]=ta;
    __syncthreads();
    if(t<DD){
        float gg = (pg[0][t]+pg[1][t])+(pg[2][t]+pg[3][t]);
        float tt = (pt[0][t]+pt[1][t])+(pt[2][t]+pt[3][t]);
        if(n>0){ g_gat[p*DD+t]=gg/den; g_trans[p*DD+t]=tt; }
        else    { g_gat[p*DD+t]=g_hmean[t]; g_trans[p*DD+t]=0.f; }
    }
}

// ---------------- K2b: coff/seqs/seqs_pos -> E1=exp(-M1), E2=exp(-M2) ----------------
__global__ void k2b_seq(const int* __restrict__ logs, const float* __restrict__ emb,
                        const float* __restrict__ pe, const float* __restrict__ ccg,
                        const float* __restrict__ cng, const float* __restrict__ w1g,
                        const float* __restrict__ w2g){
    extern __shared__ float sm[];
    float* cc=sm; float* cn=sm+4096; float* w1=sm+8192; float* w2=sm+12288;
    float* gb=sm+16384; float* tb=gb+256; float* spb=tb+256;
    int t=threadIdx.x;
    for(int k=t;k<4096;k+=256){ cc[k]=ccg[k]; cn[k]=cng[k]; w1[k]=w1g[k]; w2[k]=w2g[k]; }
    __syncthreads();
    int pl=t>>6, d=t&63;
    for(int ch=0; ch<8; ch++){
        int p = blockIdx.x*32 + ch*4 + pl;
        int i = logs[p];
        float gv=g_gat[p*DD+d], tv=g_trans[p*DD+d];
        gb[pl*DD+d]=gv; tb[pl*DD+d]=tv;
        __syncthreads();
        float x=0.f;
        #pragma unroll 8
        for(int k=0;k<DD;k++) x = fmaf(gb[pl*DD+k],cc[k*DD+d], fmaf(tb[pl*DD+k],cn[k*DD+d], x));
        float coff = 1.0f/(1.0f+__expf(-x));
        float sv = coff*gv + (1.0f-coff)*tv + emb[i*DD+d];
        g_seqs[p*DD+d]=sv;
        float spv = sv + ((i!=0)? pe[(p%LL)*DD+d] : 0.f);
        spb[pl*DD+d]=spv;
        __syncthreads();
        float m1=0.f,m2=0.f;
        #pragma unroll 8
        for(int k=0;k<DD;k++){ float s=spb[pl*DD+k]; m1=fmaf(s,w1[k*DD+d],m1); m2=fmaf(s,w2[k*DD+d],m2); }
        g_E1[p*DD+d]=__expf(-m1);
        g_E2[p*DD+d]=__expf(-m2);
        __syncthreads();
    }
}

// ---------------- K3: score (factorized sigmoid, FMA rcp) + causal attend ----------------
__global__ void k3_attn(const float* __restrict__ ba){
    extern __shared__ float sm[];
    float* E2s = sm;                  // LL*STR
    float* Ss  = E2s + LL*STR;        // LL*STR
    float* E1s = Ss  + LL*STR;        // QT*STR
    float* bs  = E1s + QT*STR;        // DD
    float* sc  = bs  + DD;            // QT*LL
    int t=threadIdx.x;
    int b=blockIdx.y;
    int q0=blockIdx.x*QT;
    int kmax = q0+QT; if(kmax>LL) kmax=LL;
    for(int idx=t; idx<kmax*DD; idx+=256){
        int k=idx>>6, d=idx&63;
        E2s[k*STR+d]=g_E2[(b*LL+k)*DD+d];
        Ss [k*STR+d]=g_seqs[(b*LL+k)*DD+d];
    }
    for(int idx=t; idx<QT*DD; idx+=256){
        int ql=idx>>6, d=idx&63;
        int q=q0+ql;
        if(q<LL) E1s[ql*STR+d]=g_E1[(b*LL+q)*DD+d];
    }
    if(t<DD) bs[t]=ba[t];
    __syncthreads();
    { // phase 1: score[q][k] = sum_d b_d / (1 + E1[q,d]*E2[k,d]),  k <= q
        int ql=t>>3, k0=t&7;
        int q=q0+ql;
        if(q<LL){
            const float4* e1p = reinterpret_cast<const float4*>(E1s + ql*STR);
            const float4* bp  = reinterpret_cast<const float4*>(bs);
            for(int k=k0;k<=q;k+=8){
                const float4* e2p = reinterpret_cast<const float4*>(E2s + k*STR);
                float acc=0.f;
                #pragma unroll
                for(int ii=0;ii<16;ii++){
                    float4 a=e1p[ii]; float4 e=e2p[ii]; float4 bb=bp[ii];
                    float u,r;
                    u=1.0f+fminf(a.x*e.x,1e30f); r=fast_rcp(u); acc=fmaf(bb.x,r,acc);
                    u=1.0f+fminf(a.y*e.y,1e30f); r=fast_rcp(u); acc=fmaf(bb.y,r,acc);
                    u=1.0f+fminf(a.z*e.z,1e30f); r=fast_rcp(u); acc=fmaf(bb.z,r,acc);
                    u=1.0f+fminf(a.w*e.w,1e30f); r=fast_rcp(u); acc=fmaf(bb.w,r,acc);
                }
                sc[ql*LL+k]=acc;
            }
        }
    }
    __syncthreads();
    { // phase 2: final[q,d] = sum_{k<=q} score[q][k] * seqs[k,d]
        int d=t&63, qg=t>>6;
        for(int qi=qg; qi<QT; qi+=4){
            int q=q0+qi;
            if(q>=LL) break;
            float acc0=0.f, acc1=0.f;
            const float* sr = sc + qi*LL;
            int k=0;
            for(; k+1<=q; k+=2){
                acc0 = fmaf(sr[k],   Ss[k*STR+d],     acc0);
                acc1 = fmaf(sr[k+1], Ss[(k+1)*STR+d], acc1);
            }
            if(k<=q) acc0 = fmaf(sr[k], Ss[k*STR+d], acc0);
            g_final[(b*LL+q)*DD+d]=acc0+acc1;
        }
    }
}

// ---------------- K4: FFN + UpDown + logits ----------------
__global__ void k4_ffn(const int* __restrict__ poss, const int* __restrict__ negs,
                       const float* __restrict__ emb,
                       const float* c1wg,const float* c1bg,const float* c2wg,const float* c2bg,
                       const float* uwg,const float* ubg,const float* gwg,const float* gbg,
                       const float* dwg,const float* dbg, float* __restrict__ out){
    extern __shared__ float sm[];
    float* c1w=sm;            float* c2w=c1w+4096;
    float* uw =c2w+4096;      float* gw =uw+8192;   float* dw=gw+8192;
    float* c1b=dw+8192;       float* c2b=c1b+64;
    float* ub =c2b+64;        float* gb2=ub+128;    float* db=gb2+128;
    float* fin=db+64;  float* f1=fin+256; float* fin2=f1+256;
    float* hb=fin2+256; float* fin3=hb+512;
    int t=threadIdx.x;
    for(int k=t;k<4096;k+=256){ c1w[k]=c1wg[k]; c2w[k]=c2wg[k]; }
    for(int k=t;k<8192;k+=256){ uw[k]=uwg[k]; gw[k]=gwg[k]; dw[k]=dwg[k]; }
    if(t<64){ c1b[t]=c1bg[t]; c2b[t]=c2bg[t]; db[t]=dbg[t]; }
    if(t<128){ ub[t]=ubg[t]; gb2[t]=gbg[t]; }
    __syncthreads();
    int pl=t>>6, d=t&63;
    for(int ch=0; ch<4; ch++){
        int p = blockIdx.x*16 + ch*4 + pl;
        fin[pl*64+d] = g_final[p*64+d];
        __syncthreads();
        float x=c1b[d];
        #pragma unroll 8
        for(int k=0;k<64;k++) x=fmaf(fin[pl*64+k], c1w[k*64+d], x);
        f1[pl*64+d]=fmaxf(x,0.f);
        __syncthreads();
        float y=c2b[d];
        #pragma unroll 8
        for(int k=0;k<64;k++) y=fmaf(f1[pl*64+k], c2w[k*64+d], y);
        fin2[pl*64+d]=fin[pl*64+d] + y;
        __syncthreads();
        {
            int dd=t&127;
            for(int plc=t>>7; plc<4; plc+=2){
                float yu=ub[dd], gg=gb2[dd];
                #pragma unroll 8
                for(int k=0;k<64;k++){ float fv=fin2[plc*64+k]; yu=fmaf(fv,uw[k*128+dd],yu); gg=fmaf(fv,gw[k*128+dd],gg); }
                gg=fmaxf(gg,0.f);
                hb[plc*128+dd]=gg*yu;
            }
        }
        __syncthreads();
        float z=db[d];
        #pragma unroll 8
        for(int k=0;k<128;k++) z=fmaf(hb[pl*128+k], dw[k*64+d], z);
        fin3[pl*64+d]=fin2[pl*64+d]+fmaxf(z,0.f);
        __syncthreads();
        {
            int w=t>>5, lane=t&31;
            int pl3=w>>1, which=w&1;
            int pp=blockIdx.x*16+ch*4+pl3;
            int idx = which? negs[pp] : poss[pp];
            float s = fin3[pl3*64+lane]*emb[idx*64+lane] + fin3[pl3*64+lane+32]*emb[idx*64+lane+32];
            #pragma unroll
            for(int o2=16;o2>0;o2>>=1) s+=__shfl_xor_sync(0xffffffffu,s,o2);
            if(lane==0) out[which*PP+pp]=s;
        }
        __syncthreads();
    }
}

// ---------------- host launcher ----------------
extern "C" void kernel_launch(void* const* d_in, const int* in_sizes, int n_in,
                              void* d_out, int out_size){
    const int*   logs = (const int*)  d_in[0];
    const int*   poss = (const int*)  d_in[1];
    const int*   negs = (const int*)  d_in[2];
    // d_in[3] = step (unused)
    const float* adj  = (const float*)d_in[4];
    const float* emb  = (const float*)d_in[5];
    const float* pe   = (const float*)d_in[6];
    const float* Wi   = (const float*)d_in[7];
    const float* ai   = (const float*)d_in[8];
    const float* W1   = (const float*)d_in[9];
    const float* W2   = (const float*)d_in[10];
    const float* ba   = (const float*)d_in[11];
    const float* ccg  = (const float*)d_in[12];
    const float* cng  = (const float*)d_in[13];
    const float* c1w  = (const float*)d_in[14];
    const float* c1b  = (const float*)d_in[15];
    const float* c2w  = (const float*)d_in[16];
    const float* c2b  = (const float*)d_in[17];
    const float* uw   = (const float*)d_in[18];
    const float* ub   = (const float*)d_in[19];
    const float* gw   = (const float*)d_in[20];
    const float* gb   = (const float*)d_in[21];
    const float* dw   = (const float*)d_in[22];
    const float* db   = (const float*)d_in[23];
    float* out = (float*)d_out;

    cudaFuncSetAttribute(k2b_seq, cudaFuncAttributeMaxDynamicSharedMemorySize, 68608);
    cudaFuncSetAttribute(k3_attn, cudaFuncAttributeMaxDynamicSharedMemorySize, 143360);
    cudaFuncSetAttribute(k4_ffn,  cudaFuncAttributeMaxDynamicSharedMemorySize, 139008);

    k1_hitem<<<(N1+3)/4, 256>>>(emb, Wi, ai);
    k1b_hmean<<<64,256>>>();
    k2a_gat<<<PP,256>>>(adj, logs);
    k2b_seq<<<PP/32,256, 68608>>>(logs, emb, pe, ccg, cng, W1, W2);
    dim3 g3((LL+QT-1)/QT, BB);
    k3_attn<<<g3,256, 143360>>>(ba);
    k4_ffn<<<PP/16,256, 139008>>>(poss, negs, emb, c1w,c1b,c2w,c2b, uw,ub,gw,gb, dw,db, out);
}